// round 1
// baseline (speedup 1.0000x reference)
#include <cuda_runtime.h>

#define BATCH 64
#define SEQ   512
#define DIN   256
#define UNITS 512

// Scan grid decomposition: 128 CTAs = 8 batch-groups x 16 unit-groups
#define N_BG 8
#define N_UG 16
#define BPG  8     // batches per group
#define UPG  32    // units (columns) per CTA
#define SCAN_THREADS 256

// Ping-pong recurrent state: [buf][bg][ (k*8 + b_local) / 4 ] as float4.
// Per bg block: 512 cols * 8 batches = 4096 floats = 1024 float4 (16 KB).
__device__ float4   g_h[2][N_BG][UNITS * BPG / 4];
__device__ unsigned g_bar[N_BG * 32];   // padded per-bg barrier counters

// ---------------------------------------------------------------------------
// Init: reset barrier counters and broadcast h0 into g_h[0] (layout [k][b]).
// Runs every launch so graph replays are deterministic.
// ---------------------------------------------------------------------------
__global__ void init_kernel(const float* __restrict__ h0) {
    int i = blockIdx.x * blockDim.x + threadIdx.x;   // 0 .. 32767
    int k = (i >> 3) & (UNITS - 1);
    ((float*)g_h)[i] = h0[k];
    if (blockIdx.x == 0 && threadIdx.x < N_BG) g_bar[threadIdx.x * 32] = 0u;
}

// ---------------------------------------------------------------------------
// Phase 0: xT = X @ T, written into d_out at [t][b][u].
// X is [BATCH][SEQ][DIN] row-major -> flat rows r = b*SEQ + t.
// Classic 64x64 tile, 256 threads, 4x4 micro-tile, fp32.
// ---------------------------------------------------------------------------
#define GK 32
__global__ __launch_bounds__(256) void gemm_kernel(
    const float* __restrict__ X, const float* __restrict__ T,
    float* __restrict__ out)
{
    __shared__ float Xs[64][GK];   // [row][kk]
    __shared__ float Ts[GK][64];   // [kk][col]

    const int tid = threadIdx.x;
    const int tx = tid & 15;       // col quad
    const int ty = tid >> 4;       // row quad
    const int row0 = blockIdx.y * 64;
    const int col0 = blockIdx.x * 64;

    float acc[4][4];
#pragma unroll
    for (int i = 0; i < 4; i++)
#pragma unroll
        for (int j = 0; j < 4; j++) acc[i][j] = 0.0f;

    for (int kc = 0; kc < DIN; kc += GK) {
#pragma unroll
        for (int q = 0; q < 2; q++) {            // X tile: 512 float4
            int j = tid + q * 256;
            int r = j >> 3, c4 = j & 7;
            float4 v = *(const float4*)(X + (size_t)(row0 + r) * DIN + kc + c4 * 4);
            *(float4*)(&Xs[r][c4 * 4]) = v;
        }
#pragma unroll
        for (int q = 0; q < 2; q++) {            // T tile: 512 float4
            int j = tid + q * 256;
            int r = j >> 4, c4 = j & 15;
            float4 v = *(const float4*)(T + (size_t)(kc + r) * UNITS + col0 + c4 * 4);
            *(float4*)(&Ts[r][c4 * 4]) = v;
        }
        __syncthreads();

#pragma unroll
        for (int kk = 0; kk < GK; kk++) {
            float a0 = Xs[ty * 4 + 0][kk];
            float a1 = Xs[ty * 4 + 1][kk];
            float a2 = Xs[ty * 4 + 2][kk];
            float a3 = Xs[ty * 4 + 3][kk];
            float4 b4 = *(float4*)(&Ts[kk][tx * 4]);
            acc[0][0] += a0 * b4.x; acc[0][1] += a0 * b4.y; acc[0][2] += a0 * b4.z; acc[0][3] += a0 * b4.w;
            acc[1][0] += a1 * b4.x; acc[1][1] += a1 * b4.y; acc[1][2] += a1 * b4.z; acc[1][3] += a1 * b4.w;
            acc[2][0] += a2 * b4.x; acc[2][1] += a2 * b4.y; acc[2][2] += a2 * b4.z; acc[2][3] += a2 * b4.w;
            acc[3][0] += a3 * b4.x; acc[3][1] += a3 * b4.y; acc[3][2] += a3 * b4.z; acc[3][3] += a3 * b4.w;
        }
        __syncthreads();
    }

    // scatter rows to [t][b][u] layout in d_out
#pragma unroll
    for (int i = 0; i < 4; i++) {
        int r = row0 + ty * 4 + i;
        int t = r & (SEQ - 1);
        int b = r >> 9;
        float* o = out + ((size_t)(t * BATCH + b)) * UNITS + col0 + tx * 4;
        *(float4*)o = make_float4(acc[i][0], acc[i][1], acc[i][2], acc[i][3]);
    }
}

// ---------------------------------------------------------------------------
// Phase 1: persistent scan. 128 CTAs, 256 threads.
// CTA (bg, ug): batches [bg*8, bg*8+8), columns [ug*32, ug*32+32).
// B slice cached in SMEM for all 512 steps. h exchanged via L2 within each
// bg-row (16 CTAs), synced by a per-bg monotone-counter barrier.
// ---------------------------------------------------------------------------
__global__ __launch_bounds__(SCAN_THREADS, 1) void scan_kernel(
    const float* __restrict__ Bm, const float* __restrict__ bias,
    float* __restrict__ out)
{
    extern __shared__ float smem[];
    float*  Bs  = smem;                          // 512*32 = 16384 floats (64 KB)
    float4* hs4 = (float4*)(smem + 16384);       // 1024 float4  (16 KB)
    float*  red = smem + 16384 + 4096;           // 2048 floats  (8 KB)
    float*  wt  = red + 2048;                    // 256 floats   (1 KB)

    const int tid  = threadIdx.x;
    const int ug   = blockIdx.x & (N_UG - 1);
    const int bg   = blockIdx.x >> 4;
    const int u    = tid & 31;            // local column
    const int kc   = tid >> 5;            // warp id == k-chunk id (8 chunks of 64)
    const int lane = tid & 31;
    const int k0   = kc * 64;

    // Load B slice: Bs[k][u_local] = B[k][ug*32 + u_local]
    for (int j = tid; j < UNITS * UPG / 4; j += SCAN_THREADS) {
        int k = j >> 3, q = j & 7;
        *(float4*)(&Bs[k * 32 + q * 4]) =
            *(const float4*)(Bm + (size_t)k * UNITS + ug * 32 + q * 4);
    }
    const float bv = bias[ug * 32 + u];

    // Epilogue mapping: thread -> (batch_local rb = kc, column u)
    const int rb = kc;
    const size_t obase = (size_t)(bg * BPG + rb) * UNITS + ug * 32 + u;

    volatile unsigned* cnt = (volatile unsigned*)&g_bar[bg * 32];
    unsigned ticket = 0;
    __syncthreads();

    for (int t = 0; t < SEQ; t++) {
        const int cb = t & 1;
        const int nb = cb ^ 1;

        // prefetch this thread's xT element (written by gemm phase)
        const size_t oidx = (size_t)t * (BATCH * UNITS) + obase;
        float xt = out[oidx];

        // stage this warp's k-range of h (warp-local: no CTA barrier needed)
        {
            const float4* src = g_h[cb][bg];
            const int base = k0 * 2;
#pragma unroll
            for (int q = 0; q < 4; q++)
                hs4[base + q * 32 + lane] = src[base + q * 32 + lane];
        }
        __syncwarp();

        // accumulate partial dot over 64 k for 8 batches, 1 column
        float a0 = 0.f, a1 = 0.f, a2 = 0.f, a3 = 0.f;
        float a4 = 0.f, a5 = 0.f, a6 = 0.f, a7 = 0.f;
        {
            const float4* hp = hs4 + k0 * 2;
            const float*  bp = Bs + k0 * 32 + u;
#pragma unroll 8
            for (int kk = 0; kk < 64; kk++) {
                float4 ha = hp[kk * 2];
                float4 hb = hp[kk * 2 + 1];
                float  w  = bp[kk * 32];
                a0 += ha.x * w; a1 += ha.y * w; a2 += ha.z * w; a3 += ha.w * w;
                a4 += hb.x * w; a5 += hb.y * w; a6 += hb.z * w; a7 += hb.w * w;
            }
        }
        // write split-K partials: red[(b*32+u)*8 + kc]
        red[(0 * 32 + u) * 8 + kc] = a0;
        red[(1 * 32 + u) * 8 + kc] = a1;
        red[(2 * 32 + u) * 8 + kc] = a2;
        red[(3 * 32 + u) * 8 + kc] = a3;
        red[(4 * 32 + u) * 8 + kc] = a4;
        red[(5 * 32 + u) * 8 + kc] = a5;
        red[(6 * 32 + u) * 8 + kc] = a6;
        red[(7 * 32 + u) * 8 + kc] = a7;
        __syncthreads();

        // reduce 8 partials for output (rb, u)
        float s;
        {
            const float* rp = red + ((rb * 32 + u) << 3);
            float4 r0 = *(const float4*)rp;
            float4 r1 = *(const float4*)(rp + 4);
            s = ((r0.x + r0.y) + (r0.z + r0.w)) + ((r1.x + r1.y) + (r1.z + r1.w));
        }

        // modrelu: sign(z) * relu(|z| + bias), with sign(0) = 0
        float z = xt + s;
        float m = fabsf(z) + bv;
        float h = (z == 0.0f) ? 0.0f : copysignf(fmaxf(m, 0.0f), z);

        out[oidx] = h;               // state output for this timestep
        wt[u * 8 + rb] = h;          // smem transpose -> coalesced h_next store
        __syncthreads();

        if (tid < 64) {
            g_h[nb][bg][ug * 64 + tid] = ((const float4*)wt)[tid];
        }
        __syncthreads();

        // per-bg barrier (16 CTAs), monotone counter, release/acquire fences
        if (tid == 0) {
            __threadfence();
            atomicAdd((unsigned*)cnt, 1u);
            ticket += N_UG;
            while (*cnt < ticket) { }
            __threadfence();
        }
        __syncthreads();
    }
}

// ---------------------------------------------------------------------------
extern "C" void kernel_launch(void* const* d_in, const int* in_sizes, int n_in,
                              void* d_out, int out_size) {
    const float* x    = (const float*)d_in[0];
    const float* T    = (const float*)d_in[1];
    const float* B    = (const float*)d_in[2];
    const float* bias = (const float*)d_in[3];
    const float* h0   = (const float*)d_in[4];
    // defensive: distinguish T (256*512) from B (512*512) by size
    if (in_sizes[1] == UNITS * UNITS && in_sizes[2] == DIN * UNITS) {
        const float* tmp = T; T = B; B = tmp;
    }
    float* out = (float*)d_out;

    const int scan_smem = (16384 + 4096 + 2048 + 256) * 4;   // 91136 B
    cudaFuncSetAttribute(scan_kernel,
                         cudaFuncAttributeMaxDynamicSharedMemorySize, scan_smem);

    init_kernel<<<64, 512>>>(h0);
    gemm_kernel<<<dim3(UNITS / 64, (BATCH * SEQ) / 64), 256>>>(x, T, out);
    scan_kernel<<<N_BG * N_UG, SCAN_THREADS, scan_smem>>>(B, bias, out);
}

// round 5
// speedup vs baseline: 1.2571x; 1.2571x over previous
#include <cuda_runtime.h>

#define BATCH 64
#define SEQ   512
#define DIN   256
#define UNITS 512

// Scan grid decomposition: 128 CTAs = 8 batch-groups x 16 unit-groups
#define N_BG 8
#define N_UG 16
#define BPG  8     // batches per group
#define UPG  32    // units (columns) per CTA
#define SCAN_THREADS 256

// Ping-pong recurrent state. Per bg block: 512 cols * 8 batches = 4096 floats.
// Layout (pair-interleaved for f32x2 consumption):
//   float index = (col>>1)*16 + b*2 + (col&1)
// i.e. [k2][b][parity] with parity = col&1 (even/odd k packed adjacently).
__device__ float4   g_h[2][N_BG][UNITS * BPG / 4];
__device__ unsigned g_bar[N_BG * 32];   // padded per-bg barrier counters

__device__ __forceinline__ void ffma2(unsigned long long& d,
                                      unsigned long long a,
                                      unsigned long long b) {
    asm("fma.rn.f32x2 %0, %1, %2, %0;" : "+l"(d) : "l"(a), "l"(b));
}

// ---------------------------------------------------------------------------
// Init: reset barrier counters, broadcast h0 into g_h (pair-interleaved).
// Runs every launch so graph replays are deterministic.
// ---------------------------------------------------------------------------
__global__ void init_kernel(const float* __restrict__ h0) {
    int i = blockIdx.x * blockDim.x + threadIdx.x;   // 0 .. 32767
#pragma unroll
    for (int q = 0; q < 2; q++) {
        int j = i + q * 32768;                        // 0 .. 65535
        int idx = j & 4095;                           // within one bg block
        int col = ((idx >> 4) << 1) | (idx & 1);
        ((float*)g_h)[j] = h0[col];
    }
    if (blockIdx.x == 0 && threadIdx.x < N_BG) g_bar[threadIdx.x * 32] = 0u;
}

// ---------------------------------------------------------------------------
// Phase 0: xT = X @ T, written into d_out at [t][b][u].
// 64x64 tile, 256 threads, 4x4 micro-tile, packed f32x2 FMAs.
// ---------------------------------------------------------------------------
#define GK 32
__global__ __launch_bounds__(256) void gemm_kernel(
    const float* __restrict__ X, const float* __restrict__ T,
    float* __restrict__ out)
{
    __shared__ __align__(16) float2 Xs2[64][GK];   // duplicated pairs, 16 KB
    __shared__ __align__(16) float  Ts[GK][64];    // 8 KB

    const int tid = threadIdx.x;
    const int tx = tid & 15;       // col quad
    const int ty = tid >> 4;       // row quad
    const int row0 = blockIdx.y * 64;
    const int col0 = blockIdx.x * 64;

    unsigned long long acc2[4][2];
#pragma unroll
    for (int i = 0; i < 4; i++) { acc2[i][0] = 0ull; acc2[i][1] = 0ull; }

    for (int kc = 0; kc < DIN; kc += GK) {
#pragma unroll
        for (int q = 0; q < 2; q++) {            // X tile: 512 float4
            int j = tid + q * 256;
            int r = j >> 3, c4 = j & 7;
            float4 v = *(const float4*)(X + (size_t)(row0 + r) * DIN + kc + c4 * 4);
            Xs2[r][c4 * 4 + 0] = make_float2(v.x, v.x);
            Xs2[r][c4 * 4 + 1] = make_float2(v.y, v.y);
            Xs2[r][c4 * 4 + 2] = make_float2(v.z, v.z);
            Xs2[r][c4 * 4 + 3] = make_float2(v.w, v.w);
        }
#pragma unroll
        for (int q = 0; q < 2; q++) {            // T tile: 512 float4
            int j = tid + q * 256;
            int r = j >> 4, c4 = j & 15;
            float4 v = *(const float4*)(T + (size_t)(kc + r) * UNITS + col0 + c4 * 4);
            *(float4*)(&Ts[r][c4 * 4]) = v;
        }
        __syncthreads();

#pragma unroll
        for (int kk = 0; kk < GK; kk++) {
            unsigned long long a0 = *reinterpret_cast<const unsigned long long*>(&Xs2[ty * 4 + 0][kk]);
            unsigned long long a1 = *reinterpret_cast<const unsigned long long*>(&Xs2[ty * 4 + 1][kk]);
            unsigned long long a2 = *reinterpret_cast<const unsigned long long*>(&Xs2[ty * 4 + 2][kk]);
            unsigned long long a3 = *reinterpret_cast<const unsigned long long*>(&Xs2[ty * 4 + 3][kk]);
            ulonglong2 bb = *reinterpret_cast<const ulonglong2*>(&Ts[kk][tx * 4]);
            ffma2(acc2[0][0], a0, bb.x); ffma2(acc2[0][1], a0, bb.y);
            ffma2(acc2[1][0], a1, bb.x); ffma2(acc2[1][1], a1, bb.y);
            ffma2(acc2[2][0], a2, bb.x); ffma2(acc2[2][1], a2, bb.y);
            ffma2(acc2[3][0], a3, bb.x); ffma2(acc2[3][1], a3, bb.y);
        }
        __syncthreads();
    }

    // scatter rows to [t][b][u] layout in d_out
#pragma unroll
    for (int i = 0; i < 4; i++) {
        int r = row0 + ty * 4 + i;
        int t = r & (SEQ - 1);
        int b = r >> 9;
        union { float4 f4; unsigned long long u[2]; } o;
        o.u[0] = acc2[i][0];
        o.u[1] = acc2[i][1];
        float* op = out + ((size_t)(t * BATCH + b)) * UNITS + col0 + tx * 4;
        *(float4*)op = o.f4;
    }
}

// ---------------------------------------------------------------------------
// Phase 1: persistent scan. 128 CTAs, 256 threads.
// CTA (bg, ug): batches [bg*8, bg*8+8), columns [ug*32, ug*32+32).
// B slice lives in REGISTERS (32 packed f32x2 pairs / thread) for all steps.
// h exchanged via L2 with .cg ops; per-bg release/acquire counter barrier
// (no gpu-scope fences -> no CCTL.IVALL L1 flushes).
// ---------------------------------------------------------------------------
__global__ __launch_bounds__(SCAN_THREADS, 1) void scan_kernel(
    const float* __restrict__ Bm, const float* __restrict__ bias,
    float* __restrict__ out)
{
    __shared__ __align__(16) float hs[UNITS * BPG];   // 16 KB staged h
    __shared__ float red[256 * 9];                    // padded split-K partials

    const int tid  = threadIdx.x;
    const int ug   = blockIdx.x & (N_UG - 1);
    const int bg   = blockIdx.x >> 4;
    const int u    = tid & 31;            // local column (lane)
    const int kc   = tid >> 5;            // warp id == k-chunk id (8 x 64)
    const int lane = tid & 31;
    const int c    = ug * 32 + u;         // global column
    const int k0   = kc * 64;

    // B slice into registers: w2[j] = packed {B[k0+2j][c], B[k0+2j+1][c]}
    unsigned long long w2[32];
#pragma unroll
    for (int j = 0; j < 32; j++) {
        float2 t2 = make_float2(Bm[(size_t)(k0 + 2 * j) * UNITS + c],
                                Bm[(size_t)(k0 + 2 * j + 1) * UNITS + c]);
        w2[j] = *reinterpret_cast<unsigned long long*>(&t2);
    }
    const float bv = bias[c];

    // Epilogue mapping: thread -> (batch_local rb = kc, column c)
    const size_t obase = (size_t)(bg * BPG + kc) * UNITS + c;
    unsigned* cnt = &g_bar[bg * 32];
    float* hb0 = (float*)&g_h[0][bg][0];
    float* hb1 = (float*)&g_h[1][bg][0];
    const int hidx = ((c >> 1) * 16) + kc * 2 + (c & 1);   // pair-interleaved slot

    for (int t = 0; t < SEQ; t++) {
        const size_t oidx = (size_t)t * (BATCH * UNITS) + obase;
        float xt = out[oidx];             // prefetch before barrier wait

        if (t > 0) {
            if (tid == 0) {
                unsigned target = (unsigned)t * N_UG;
                unsigned v;
                do {
                    asm volatile("ld.acquire.gpu.global.u32 %0, [%1];"
                                 : "=r"(v) : "l"(cnt) : "memory");
                } while (v < target);
            }
            __syncthreads();
        }

        const float* hsrc = (t & 1) ? hb1 : hb0;
        float*       hdst = (t & 1) ? hb0 : hb1;

        // stage this warp's k-chunk of h (warp-local, L2 reads)
        {
            const float4* src4 = (const float4*)hsrc + kc * 128;
            float4*       dst4 = (float4*)hs + kc * 128;
#pragma unroll
            for (int q = 0; q < 4; q++)
                dst4[q * 32 + lane] = __ldcg(src4 + q * 32 + lane);
        }
        __syncwarp();

        // packed split-K dot: 64 k (32 pairs) x 8 batches x 1 column
        unsigned long long acc[8];
#pragma unroll
        for (int b = 0; b < 8; b++) acc[b] = 0ull;
        const ulonglong2* hp = (const ulonglong2*)hs + kc * 128;
#pragma unroll
        for (int j = 0; j < 32; j++) {
            ulonglong2 v0 = hp[j * 4 + 0];
            ulonglong2 v1 = hp[j * 4 + 1];
            ulonglong2 v2 = hp[j * 4 + 2];
            ulonglong2 v3 = hp[j * 4 + 3];
            ffma2(acc[0], v0.x, w2[j]); ffma2(acc[1], v0.y, w2[j]);
            ffma2(acc[2], v1.x, w2[j]); ffma2(acc[3], v1.y, w2[j]);
            ffma2(acc[4], v2.x, w2[j]); ffma2(acc[5], v2.y, w2[j]);
            ffma2(acc[6], v3.x, w2[j]); ffma2(acc[7], v3.y, w2[j]);
        }

        // write split-K partials (pad 9 -> conflict-free)
#pragma unroll
        for (int b = 0; b < 8; b++) {
            float2 f = *reinterpret_cast<float2*>(&acc[b]);
            red[(b * 32 + u) * 9 + kc] = f.x + f.y;
        }
        __syncthreads();

        // reduce 8 partials for output (rb = kc, u)
        float s = 0.0f;
        {
            const float* rp = red + (kc * 32 + u) * 9;
#pragma unroll
            for (int k = 0; k < 8; k++) s += rp[k];
        }

        // modrelu: sign(z) * relu(|z| + bias), with sign(0) = 0
        float z = xt + s;
        float m = fabsf(z) + bv;
        float h = (z == 0.0f) ? 0.0f : copysignf(fmaxf(m, 0.0f), z);

        __stcg(hdst + hidx, h);           // next-state exchange (L2)
        __syncthreads();                  // all stores issued before arrive

        if (tid == 0)
            asm volatile("red.release.gpu.global.add.u32 [%0], 1;"
                         :: "l"(cnt) : "memory");

        out[oidx] = h;                    // state output, off critical path
    }
}

// ---------------------------------------------------------------------------
extern "C" void kernel_launch(void* const* d_in, const int* in_sizes, int n_in,
                              void* d_out, int out_size) {
    const float* x    = (const float*)d_in[0];
    const float* T    = (const float*)d_in[1];
    const float* B    = (const float*)d_in[2];
    const float* bias = (const float*)d_in[3];
    const float* h0   = (const float*)d_in[4];
    // defensive: distinguish T (256*512) from B (512*512) by size
    if (in_sizes[1] == UNITS * UNITS && in_sizes[2] == DIN * UNITS) {
        const float* tmp = T; T = B; B = tmp;
    }
    float* out = (float*)d_out;

    init_kernel<<<64, 512>>>(h0);
    gemm_kernel<<<dim3(UNITS / 64, (BATCH * SEQ) / 64), 256>>>(x, T, out);
    scan_kernel<<<N_BG * N_UG, SCAN_THREADS>>>(B, bias, out);
}

// round 8
// speedup vs baseline: 1.5223x; 1.2109x over previous
#include <cuda_runtime.h>

#define BATCH 64
#define SEQ   512
#define DIN   256
#define UNITS 512

#define NCTA    128
#define N_BG    16       // batch groups
#define N_UG    8        // unit groups
#define BPG     4        // batches per CTA
#define UPG     64       // columns per CTA
#define THREADS 256

// Ping-pong recurrent state. Per bg block: 512 cols * 4 batches = 2048 floats.
// Layout (pair-interleaved for f32x2): float idx = (c>>1)*8 + b*2 + (c&1).
__device__ float4   g_h[2][N_BG][UNITS * BPG / 4];
__device__ unsigned g_flag[NCTA * 32];   // per-(bg,ug) producer step counters
__device__ unsigned g_gbar;              // monotone grid barrier (never reset)

__device__ __forceinline__ void ffma2(unsigned long long& d,
                                      unsigned long long a,
                                      unsigned long long b) {
    asm("fma.rn.f32x2 %0, %1, %2, %0;" : "+l"(d) : "l"(a), "l"(b));
}

__device__ __forceinline__ unsigned ld_acq(const unsigned* p) {
    unsigned v;
    asm volatile("ld.acquire.gpu.global.u32 %0, [%1];" : "=r"(v) : "l"(p) : "memory");
    return v;
}

__global__ __launch_bounds__(THREADS, 1) void fused_kernel(
    const float* __restrict__ X, const float* __restrict__ Tm,
    const float* __restrict__ Bm, const float* __restrict__ bias,
    const float* __restrict__ h0, float* __restrict__ out)
{
    extern __shared__ char sm[];
    const int tid = threadIdx.x;
    const int cta = blockIdx.x;
    const int bg  = cta >> 3;
    const int ug  = cta & 7;

    // ---- Phase A0: reset own flag, write own h0 chunk ------------------
    if (tid == 0) g_flag[cta * 32] = 0u;
    {
        int b = tid >> 6, cc = tid & 63;
        ((float*)&g_h[0][bg][0])[ug * 256 + (cc >> 1) * 8 + b * 2 + (cc & 1)]
            = h0[ug * 64 + cc];
    }

    // ---- Phase A1: GEMM  xT -> out[t][b][u] ----------------------------
    {
        float*  Ts  = (float*)sm;                 // [256][64]   64 KB (resident)
        float2* Xs2 = (float2*)(sm + 65536);      // 2 x [64][32] dup-pairs, 32 KB

        const int tx = tid & 15, ty = tid >> 4;
        const int col0 = ug * 64;

#pragma unroll
        for (int i = 0; i < 16; i++) {            // T slice, loaded once
            int j = tid + i * 256;
            int k = j >> 4, c4 = j & 15;
            *(float4*)&Ts[k * 64 + c4 * 4] =
                *(const float4*)(Tm + (size_t)k * UNITS + col0 + c4 * 4);
        }
        __syncthreads();

        for (int q = 0; q < 32; q++) {
            const int row0 = ((cta >> 3) + 16 * q) * 64;

            // preload k-chunk 0 into stage 0
#pragma unroll
            for (int p = 0; p < 2; p++) {
                int j = tid + p * 256;
                int r = j >> 3, c4 = j & 7;
                float4 v = *(const float4*)(X + (size_t)(row0 + r) * DIN + c4 * 4);
                float2* d = Xs2 + r * 32 + c4 * 4;
                d[0] = make_float2(v.x, v.x); d[1] = make_float2(v.y, v.y);
                d[2] = make_float2(v.z, v.z); d[3] = make_float2(v.w, v.w);
            }
            __syncthreads();

            unsigned long long acc2[4][2];
#pragma unroll
            for (int i = 0; i < 4; i++) { acc2[i][0] = 0ull; acc2[i][1] = 0ull; }

            for (int kc = 0; kc < 8; kc++) {
                float4 nv[2];
                if (kc < 7) {
#pragma unroll
                    for (int p = 0; p < 2; p++) {
                        int j = tid + p * 256;
                        int r = j >> 3, c4 = j & 7;
                        nv[p] = *(const float4*)(X + (size_t)(row0 + r) * DIN
                                                   + (kc + 1) * 32 + c4 * 4);
                    }
                }
                const float2* Xc = Xs2 + (kc & 1) * 2048;
#pragma unroll
                for (int kk = 0; kk < 32; kk++) {
                    unsigned long long a0 = *(const unsigned long long*)&Xc[(ty * 4 + 0) * 32 + kk];
                    unsigned long long a1 = *(const unsigned long long*)&Xc[(ty * 4 + 1) * 32 + kk];
                    unsigned long long a2 = *(const unsigned long long*)&Xc[(ty * 4 + 2) * 32 + kk];
                    unsigned long long a3 = *(const unsigned long long*)&Xc[(ty * 4 + 3) * 32 + kk];
                    ulonglong2 bb = *(const ulonglong2*)&Ts[(kc * 32 + kk) * 64 + tx * 4];
                    ffma2(acc2[0][0], a0, bb.x); ffma2(acc2[0][1], a0, bb.y);
                    ffma2(acc2[1][0], a1, bb.x); ffma2(acc2[1][1], a1, bb.y);
                    ffma2(acc2[2][0], a2, bb.x); ffma2(acc2[2][1], a2, bb.y);
                    ffma2(acc2[3][0], a3, bb.x); ffma2(acc2[3][1], a3, bb.y);
                }
                if (kc < 7) {
                    float2* d = Xs2 + ((kc + 1) & 1) * 2048;
#pragma unroll
                    for (int p = 0; p < 2; p++) {
                        int j = tid + p * 256;
                        int r = j >> 3, c4 = j & 7;
                        float2* dd = d + r * 32 + c4 * 4;
                        dd[0] = make_float2(nv[p].x, nv[p].x);
                        dd[1] = make_float2(nv[p].y, nv[p].y);
                        dd[2] = make_float2(nv[p].z, nv[p].z);
                        dd[3] = make_float2(nv[p].w, nv[p].w);
                    }
                }
                __syncthreads();
            }

#pragma unroll
            for (int i = 0; i < 4; i++) {         // scatter to [t][b][u]
                int r = row0 + ty * 4 + i;
                int t = r & (SEQ - 1);
                int b = r >> 9;
                union { float4 f4; unsigned long long u2[2]; } o;
                o.u2[0] = acc2[i][0]; o.u2[1] = acc2[i][1];
                *(float4*)(out + ((size_t)(t * BATCH + b)) * UNITS + col0 + tx * 4) = o.f4;
            }
        }
    }

    // ---- grid barrier (monotone, +128 per launch) ----------------------
    __syncthreads();
    if (tid == 0) {
        unsigned old;
        asm volatile("atom.release.gpu.global.add.u32 %0, [%1], 1;"
                     : "=r"(old) : "l"(&g_gbar) : "memory");
        unsigned target = (old & ~(unsigned)(NCTA - 1)) + NCTA;
        while (ld_acq(&g_gbar) < target) { }
    }
    __syncthreads();

    // ---- Phase B: recurrence scan --------------------------------------
    {
        float* hs  = (float*)sm;            // 2048 floats staged h (8 KB)
        float* red = (float*)(sm + 8192);   // 2304 floats split-K partials

        const int u  = tid & 31;
        const int kc = tid >> 5;            // warp id == k-chunk == producer ug
        const int c0 = ug * 64 + u;         // this thread's two B columns
        const int k0 = kc * 64;

        // B slice in registers: 2 cols x 32 packed k-pairs
        unsigned long long w2a[32], w2b[32];
#pragma unroll
        for (int j = 0; j < 32; j++) {
            float2 p0 = make_float2(__ldg(Bm + (size_t)(k0 + 2 * j) * UNITS + c0),
                                    __ldg(Bm + (size_t)(k0 + 2 * j + 1) * UNITS + c0));
            float2 p1 = make_float2(__ldg(Bm + (size_t)(k0 + 2 * j) * UNITS + c0 + 32),
                                    __ldg(Bm + (size_t)(k0 + 2 * j + 1) * UNITS + c0 + 32));
            w2a[j] = *(unsigned long long*)&p0;
            w2b[j] = *(unsigned long long*)&p1;
        }

        const int bo = tid >> 6;            // epilogue (batch, col) ownership
        const int co = tid & 63;
        const float bv = bias[ug * 64 + co];
        const size_t obase = (size_t)(bg * BPG + bo) * UNITS + ug * 64 + co;
        const int hidx = ug * 256 + (co >> 1) * 8 + bo * 2 + (co & 1);
        unsigned* consFlag = &g_flag[(bg * 8 + kc) * 32];
        unsigned* prodFlag = &g_flag[cta * 32];
        float* hb0 = (float*)&g_h[0][bg][0];
        float* hb1 = (float*)&g_h[1][bg][0];

        for (int t = 0; t < SEQ; t++) {
            const size_t oidx = (size_t)t * (BATCH * UNITS) + obase;
            float xt = __ldcg(out + oidx);          // prefetch under the wait

            // per-warp wait on the single producer of this warp's k-chunk
            if (t > 0) { while (ld_acq(consFlag) < (unsigned)t) { } }

            const float* hsrc = (t & 1) ? hb1 : hb0;
            float*       hdst = (t & 1) ? hb0 : hb1;

            {   // stage own 1 KB chunk (64k x 4b), warp-local
                const float4* s4 = (const float4*)hsrc + kc * 64;
                float4* d4 = (float4*)hs + kc * 64;
                d4[u]      = __ldcg(s4 + u);
                d4[u + 32] = __ldcg(s4 + u + 32);
            }
            __syncwarp();

            unsigned long long a0=0,a1=0,a2=0,a3=0,a4=0,a5=0,a6=0,a7=0;
            const ulonglong2* hp = (const ulonglong2*)hs + kc * 64;
#pragma unroll
            for (int j = 0; j < 32; j++) {
                ulonglong2 v0 = hp[2 * j];          // batches 0,1 (k-pair packed)
                ulonglong2 v1 = hp[2 * j + 1];      // batches 2,3
                ffma2(a0, v0.x, w2a[j]); ffma2(a1, v0.y, w2a[j]);
                ffma2(a2, v1.x, w2a[j]); ffma2(a3, v1.y, w2a[j]);
                ffma2(a4, v0.x, w2b[j]); ffma2(a5, v0.y, w2b[j]);
                ffma2(a6, v1.x, w2b[j]); ffma2(a7, v1.y, w2b[j]);
            }
            {   // split-K partials, 9-padded (conflict-free)
                float2 f;
                f = *(float2*)&a0; red[(0 * 64 + u) * 9 + kc] = f.x + f.y;
                f = *(float2*)&a1; red[(1 * 64 + u) * 9 + kc] = f.x + f.y;
                f = *(float2*)&a2; red[(2 * 64 + u) * 9 + kc] = f.x + f.y;
                f = *(float2*)&a3; red[(3 * 64 + u) * 9 + kc] = f.x + f.y;
                f = *(float2*)&a4; red[(0 * 64 + u + 32) * 9 + kc] = f.x + f.y;
                f = *(float2*)&a5; red[(1 * 64 + u + 32) * 9 + kc] = f.x + f.y;
                f = *(float2*)&a6; red[(2 * 64 + u + 32) * 9 + kc] = f.x + f.y;
                f = *(float2*)&a7; red[(3 * 64 + u + 32) * 9 + kc] = f.x + f.y;
            }
            __syncthreads();

            float s = 0.0f;
            {
                const float* rp = red + tid * 9;
#pragma unroll
                for (int k = 0; k < 8; k++) s += rp[k];
            }

            // modrelu: sign(z) * relu(|z| + bias), sign(0) = 0
            float z = xt + s;
            float m = fabsf(z) + bv;
            float h = (z == 0.0f) ? 0.0f : copysignf(fmaxf(m, 0.0f), z);

            __stcg(hdst + hidx, h);                 // publish next state (L2)
            __syncthreads();                        // all 256 stores issued
            if (tid == 0)
                asm volatile("red.release.gpu.global.add.u32 [%0], 1;"
                             :: "l"(prodFlag) : "memory");
            out[oidx] = h;                          // off critical path
        }
    }
}

// ---------------------------------------------------------------------------
extern "C" void kernel_launch(void* const* d_in, const int* in_sizes, int n_in,
                              void* d_out, int out_size) {
    const float* x    = (const float*)d_in[0];
    const float* T    = (const float*)d_in[1];
    const float* B    = (const float*)d_in[2];
    const float* bias = (const float*)d_in[3];
    const float* h0   = (const float*)d_in[4];
    if (in_sizes[1] == UNITS * UNITS && in_sizes[2] == DIN * UNITS) {
        const float* tmp = T; T = B; B = tmp;
    }
    float* out = (float*)d_out;

    const int smem = 65536 + 32768;   // 96 KB: T slice + X double buffer / scan
    cudaFuncSetAttribute(fused_kernel,
                         cudaFuncAttributeMaxDynamicSharedMemorySize, smem);
    fused_kernel<<<NCTA, THREADS, smem>>>(x, T, B, bias, h0, out);
}